// round 4
// baseline (speedup 1.0000x reference)
#include <cuda_runtime.h>
#include <cstdint>

#define CN0 200000
#define CN1 50000
#define CN2 12500
#define CE0 3200000
#define CE1 800000
#define CE2 200000

// ---------------- scratch (__device__ globals; no allocation allowed) ----------------
__device__ __align__(16) float g_A0[CN0 * 128];
__device__ __align__(16) float g_B0[CN0 * 128];
__device__ __align__(16) float g_E0[CN0 * 128];
__device__ __align__(16) float g_T0[CN0 * 4];
__device__ __align__(16) float g_X1[CN1 * 128];
__device__ __align__(16) float g_A1[CN1 * 128];
__device__ __align__(16) float g_B1[CN1 * 128];
__device__ __align__(16) float g_E1[CN1 * 128];
__device__ __align__(16) float g_X2[CN2 * 128];
__device__ __align__(16) float g_A2[CN2 * 128];
__device__ __align__(16) float g_BT[CN2 * 128];

__device__ int   g_deg0[CN0]; __device__ int g_rp0[CN0 + 1]; __device__ int g_cur0[CN0];
__device__ int   g_col0[CE0]; __device__ float g_ws0[CE0];   __device__ float g_inv0[CN0];
__device__ int   g_deg1[CN1]; __device__ int g_rp1[CN1 + 1]; __device__ int g_cur1[CN1];
__device__ int   g_col1[CE1]; __device__ float g_ws1[CE1];   __device__ float g_inv1[CN1];
__device__ int   g_deg2[CN2]; __device__ int g_rp2[CN2 + 1]; __device__ int g_cur2[CN2];
__device__ int   g_col2[CE2]; __device__ float g_ws2[CE2];   __device__ float g_inv2[CN2];

__device__ int g_bsum0[64];
__device__ int g_bsum1[16];
__device__ int g_bsum2[8];

#define SCAN_CHUNK 4096

// ---------------- CSR build ----------------
__global__ void k_deg(const int* __restrict__ dst, int* __restrict__ deg, int E) {
    int i = blockIdx.x * blockDim.x + threadIdx.x;
    if (i < E) atomicAdd(&deg[dst[i]], 1);
}

__global__ void k_scan_part(const int* __restrict__ deg, int* __restrict__ bsum, int n) {
    __shared__ int wsum[32];
    int base = blockIdx.x * SCAN_CHUNK + threadIdx.x * 4;
    int s = 0;
#pragma unroll
    for (int j = 0; j < 4; j++) if (base + j < n) s += deg[base + j];
    int lane = threadIdx.x & 31, wid = threadIdx.x >> 5;
#pragma unroll
    for (int off = 16; off > 0; off >>= 1) s += __shfl_down_sync(0xFFFFFFFFu, s, off);
    if (lane == 0) wsum[wid] = s;
    __syncthreads();
    if (threadIdx.x < 32) {
        int v = wsum[threadIdx.x];
#pragma unroll
        for (int off = 16; off > 0; off >>= 1) v += __shfl_down_sync(0xFFFFFFFFu, v, off);
        if (threadIdx.x == 0) bsum[blockIdx.x] = v;
    }
}

__global__ void k_scan_top(int* __restrict__ bsum, int nb, int* __restrict__ rp, int n) {
    int t = threadIdx.x;
    __shared__ int sh[64];
    sh[t] = (t < nb) ? bsum[t] : 0;
    __syncthreads();
    for (int off = 1; off < 64; off <<= 1) {
        int v = (t >= off) ? sh[t - off] : 0;
        __syncthreads();
        sh[t] += v;
        __syncthreads();
    }
    if (t < nb) bsum[t] = (t == 0) ? 0 : sh[t - 1];
    if (t == 63) rp[n] = sh[63];
}

__global__ void k_scan_down(const int* __restrict__ deg, const int* __restrict__ bsum,
                            int* __restrict__ rp, int* __restrict__ cur,
                            float* __restrict__ inv, int n) {
    __shared__ int wsum[32];
    int base = blockIdx.x * SCAN_CHUNK + threadIdx.x * 4;
    int d[4];
#pragma unroll
    for (int j = 0; j < 4; j++) d[j] = (base + j < n) ? deg[base + j] : 0;
    int tot = d[0] + d[1] + d[2] + d[3];
    int lane = threadIdx.x & 31, wid = threadIdx.x >> 5;
    int sc = tot;
#pragma unroll
    for (int off = 1; off < 32; off <<= 1) {
        int v = __shfl_up_sync(0xFFFFFFFFu, sc, off);
        if (lane >= off) sc += v;
    }
    if (lane == 31) wsum[wid] = sc;
    __syncthreads();
    if (threadIdx.x < 32) {
        int v = wsum[threadIdx.x];
#pragma unroll
        for (int off = 1; off < 32; off <<= 1) {
            int u = __shfl_up_sync(0xFFFFFFFFu, v, off);
            if (threadIdx.x >= off) v += u;
        }
        wsum[threadIdx.x] = v;
    }
    __syncthreads();
    int run = bsum[blockIdx.x] + (sc - tot) + (wid > 0 ? wsum[wid - 1] : 0);
#pragma unroll
    for (int j = 0; j < 4; j++) {
        if (base + j < n) {
            rp[base + j] = run;
            cur[base + j] = run;
            inv[base + j] = rsqrtf((float)(d[j] + 1));
            run += d[j];
        }
    }
}

__global__ void k_fill(const int* __restrict__ src, const int* __restrict__ dst,
                       int* __restrict__ cur, int* __restrict__ col,
                       float* __restrict__ ws, const float* __restrict__ inv, int E) {
    int i = blockIdx.x * blockDim.x + threadIdx.x;
    if (i >= E) return;
    int d = dst[i], s = src[i];
    int p = atomicAdd(&cur[d], 1);
    col[p] = s;
    ws[p] = inv[s];
}

// ---------------- aggregation over 4-wide features ----------------
__global__ void k_agg4(const float4* __restrict__ x, float4* __restrict__ out,
                       const int* __restrict__ rp, const int* __restrict__ col,
                       const float* __restrict__ ws, const float* __restrict__ inv, int n) {
    int r = blockIdx.x * blockDim.x + threadIdx.x;
    if (r >= n) return;
    float invd = inv[r];
    float4 xv = x[r];
    float c0 = invd * invd;
    float4 acc = make_float4(xv.x * c0, xv.y * c0, xv.z * c0, xv.w * c0);
    int e = rp[r], end = rp[r + 1];
    for (; e + 4 <= end; e += 4) {
        int s0 = col[e], s1 = col[e + 1], s2 = col[e + 2], s3 = col[e + 3];
        float w0 = ws[e] * invd, w1 = ws[e + 1] * invd, w2 = ws[e + 2] * invd, w3 = ws[e + 3] * invd;
        float4 v0 = x[s0], v1 = x[s1], v2 = x[s2], v3 = x[s3];
        acc.x += v0.x * w0 + v1.x * w1 + v2.x * w2 + v3.x * w3;
        acc.y += v0.y * w0 + v1.y * w1 + v2.y * w2 + v3.y * w3;
        acc.z += v0.z * w0 + v1.z * w1 + v2.z * w2 + v3.z * w3;
        acc.w += v0.w * w0 + v1.w * w1 + v2.w * w2 + v3.w * w3;
    }
    for (; e < end; e++) {
        int s0 = col[e]; float w0 = ws[e] * invd;
        float4 v0 = x[s0];
        acc.x += v0.x * w0; acc.y += v0.y * w0; acc.z += v0.z * w0; acc.w += v0.w * w0;
    }
    out[r] = acc;
}

// ---------------- aggregation over 128-wide features + bias + relu ----------------
__global__ void k_agg128(const float4* __restrict__ h, float4* __restrict__ out,
                         const int* __restrict__ rp, const int* __restrict__ col,
                         const float* __restrict__ ws, const float* __restrict__ inv,
                         const float* __restrict__ bias, int n) {
    int row = blockIdx.x * blockDim.y + threadIdx.y;
    if (row >= n) return;
    int lane = threadIdx.x;
    float invd = inv[row];
    float c0 = invd * invd;
    float4 hd = h[row * 32 + lane];
    float4 acc = make_float4(hd.x * c0, hd.y * c0, hd.z * c0, hd.w * c0);
    int e = rp[row], end = rp[row + 1];
    for (; e + 4 <= end; e += 4) {
        int s0 = col[e], s1 = col[e + 1], s2 = col[e + 2], s3 = col[e + 3];
        float w0 = ws[e] * invd, w1 = ws[e + 1] * invd, w2 = ws[e + 2] * invd, w3 = ws[e + 3] * invd;
        float4 v0 = h[s0 * 32 + lane];
        float4 v1 = h[s1 * 32 + lane];
        float4 v2 = h[s2 * 32 + lane];
        float4 v3 = h[s3 * 32 + lane];
        acc.x += v0.x * w0 + v1.x * w1 + v2.x * w2 + v3.x * w3;
        acc.y += v0.y * w0 + v1.y * w1 + v2.y * w2 + v3.y * w3;
        acc.z += v0.z * w0 + v1.z * w1 + v2.z * w2 + v3.z * w3;
        acc.w += v0.w * w0 + v1.w * w1 + v2.w * w2 + v3.w * w3;
    }
    for (; e < end; e++) {
        int s0 = col[e]; float w0 = ws[e] * invd;
        float4 v0 = h[s0 * 32 + lane];
        acc.x += v0.x * w0; acc.y += v0.y * w0; acc.z += v0.z * w0; acc.w += v0.w * w0;
    }
    int cb = lane * 4;
    acc.x = fmaxf(acc.x + bias[cb + 0], 0.f);
    acc.y = fmaxf(acc.y + bias[cb + 1], 0.f);
    acc.z = fmaxf(acc.z + bias[cb + 2], 0.f);
    acc.w = fmaxf(acc.w + bias[cb + 3], 0.f);
    out[row * 32 + lane] = acc;
}

// ---------------- K=4 GEMM with bias+relu ----------------
__global__ void k_gemm4(const float4* __restrict__ t, const float* __restrict__ W,
                        const float* __restrict__ bias, float4* __restrict__ out, int n) {
    __shared__ float Ws[4 * 128];
    __shared__ float Bs[128];
    int tid = threadIdx.x;
    for (int i = tid; i < 512; i += blockDim.x) Ws[i] = W[i];
    if (tid < 128) Bs[tid] = bias[tid];
    __syncthreads();
    int idx = blockIdx.x * blockDim.x + tid;
    int node = idx >> 5, lane = idx & 31;
    if (node >= n) return;
    float4 xv = t[node];
    int cb = lane * 4;
    float o[4];
#pragma unroll
    for (int j = 0; j < 4; j++) {
        o[j] = Bs[cb + j]
             + xv.x * Ws[0 * 128 + cb + j]
             + xv.y * Ws[1 * 128 + cb + j]
             + xv.z * Ws[2 * 128 + cb + j]
             + xv.w * Ws[3 * 128 + cb + j];
        o[j] = fmaxf(o[j], 0.f);
    }
    out[node * 32 + lane] = make_float4(o[0], o[1], o[2], o[3]);
}

// =====================================================================
//  tf32 mma.sync GEMM (sm_80 ISA, tensor pipe):
//  C[n,128] = A[n,128] @ W[128,128] (+ gathered add), 3xTF32 split.
//  Block: 256 thr / 8 warps. Tile 128x128. Warp tile 32x64.
//  Smem strides: A pad->36 (bank=(4g+t), conflict-free),
//                B pad->136 (bank=(8t+g), conflict-free).
// =====================================================================
#define MA_STR 36
#define MB_STR 136
#define SM_AH 0
#define SM_AL (128 * MA_STR * 4)
#define SM_BH (2 * 128 * MA_STR * 4)
#define SM_BL (2 * 128 * MA_STR * 4 + 32 * MB_STR * 4)
#define SM_TOT (2 * 128 * MA_STR * 4 + 2 * 32 * MB_STR * 4)

__device__ __forceinline__ void tf32_split(float v, uint32_t& hb, uint32_t& lb) {
    asm("cvt.rna.tf32.f32 %0, %1;" : "=r"(hb) : "f"(v));
    float lf = v - __uint_as_float(hb);
    asm("cvt.rna.tf32.f32 %0, %1;" : "=r"(lb) : "f"(lf));
}

__device__ __forceinline__ void mma_16n8k8(float* c, const uint32_t* a, const uint32_t* b) {
    asm volatile(
        "mma.sync.aligned.m16n8k8.row.col.f32.tf32.tf32.f32 "
        "{%0,%1,%2,%3}, {%4,%5,%6,%7}, {%8,%9}, {%0,%1,%2,%3};"
        : "+f"(c[0]), "+f"(c[1]), "+f"(c[2]), "+f"(c[3])
        : "r"(a[0]), "r"(a[1]), "r"(a[2]), "r"(a[3]), "r"(b[0]), "r"(b[1]));
}

template <bool ADD_GATHER>
__global__ void __launch_bounds__(256) k_gemm_mma(
    const float* __restrict__ A, const float* __restrict__ W,
    float* __restrict__ Cm, int n,
    const float* __restrict__ addsrc, const int* __restrict__ gidx) {
    extern __shared__ char smem[];
    uint32_t* AH = (uint32_t*)(smem + SM_AH);
    uint32_t* AL = (uint32_t*)(smem + SM_AL);
    uint32_t* BH = (uint32_t*)(smem + SM_BH);
    uint32_t* BL = (uint32_t*)(smem + SM_BL);

    int tid = threadIdx.x;
    int warp = tid >> 5, lane = tid & 31;
    int g = lane >> 2, t = lane & 3;
    int mrow = (warp & 3) * 32;      // warp row base within tile
    int ncol = (warp >> 2) * 64;     // warp col base within tile
    int r0 = blockIdx.x * 128;

    float c[2][8][4];
#pragma unroll
    for (int i = 0; i < 2; i++)
#pragma unroll
        for (int j = 0; j < 8; j++)
#pragma unroll
            for (int q = 0; q < 4; q++) c[i][j][q] = 0.f;

    for (int kc = 0; kc < 128; kc += 32) {
        __syncthreads();
        // cooperative load+split A chunk [128 rows, 32 k]
#pragma unroll
        for (int it = 0; it < 4; it++) {
            int idx = tid + it * 256;          // 0..1023 float4s
            int row = idx >> 3, kq = (idx & 7) * 4;
            float4 av = make_float4(0.f, 0.f, 0.f, 0.f);
            if (r0 + row < n) av = *(const float4*)&A[(size_t)(r0 + row) * 128 + kc + kq];
            uint32_t hb, lb;
            tf32_split(av.x, hb, lb); AH[row * MA_STR + kq + 0] = hb; AL[row * MA_STR + kq + 0] = lb;
            tf32_split(av.y, hb, lb); AH[row * MA_STR + kq + 1] = hb; AL[row * MA_STR + kq + 1] = lb;
            tf32_split(av.z, hb, lb); AH[row * MA_STR + kq + 2] = hb; AL[row * MA_STR + kq + 2] = lb;
            tf32_split(av.w, hb, lb); AH[row * MA_STR + kq + 3] = hb; AL[row * MA_STR + kq + 3] = lb;
        }
        // cooperative load+split W chunk [32 k, 128 n]
#pragma unroll
        for (int it = 0; it < 4; it++) {
            int idx = tid + it * 256;
            int k = idx >> 5, nn = (idx & 31) * 4;
            float4 wv = *(const float4*)&W[(size_t)(kc + k) * 128 + nn];
            uint32_t hb, lb;
            tf32_split(wv.x, hb, lb); BH[k * MB_STR + nn + 0] = hb; BL[k * MB_STR + nn + 0] = lb;
            tf32_split(wv.y, hb, lb); BH[k * MB_STR + nn + 1] = hb; BL[k * MB_STR + nn + 1] = lb;
            tf32_split(wv.z, hb, lb); BH[k * MB_STR + nn + 2] = hb; BL[k * MB_STR + nn + 2] = lb;
            tf32_split(wv.w, hb, lb); BH[k * MB_STR + nn + 3] = hb; BL[k * MB_STR + nn + 3] = lb;
        }
        __syncthreads();

#pragma unroll
        for (int ks = 0; ks < 4; ks++) {
            int k8 = ks * 8;
            uint32_t ah[2][4], al[2][4];
#pragma unroll
            for (int i = 0; i < 2; i++) {
                int ra = mrow + i * 16 + g;
                ah[i][0] = AH[ra * MA_STR + k8 + t];
                ah[i][1] = AH[(ra + 8) * MA_STR + k8 + t];
                ah[i][2] = AH[ra * MA_STR + k8 + t + 4];
                ah[i][3] = AH[(ra + 8) * MA_STR + k8 + t + 4];
                al[i][0] = AL[ra * MA_STR + k8 + t];
                al[i][1] = AL[(ra + 8) * MA_STR + k8 + t];
                al[i][2] = AL[ra * MA_STR + k8 + t + 4];
                al[i][3] = AL[(ra + 8) * MA_STR + k8 + t + 4];
            }
#pragma unroll
            for (int j = 0; j < 8; j++) {
                int cn = ncol + j * 8 + g;
                uint32_t bh[2], bl[2];
                bh[0] = BH[(k8 + t) * MB_STR + cn];
                bh[1] = BH[(k8 + t + 4) * MB_STR + cn];
                bl[0] = BL[(k8 + t) * MB_STR + cn];
                bl[1] = BL[(k8 + t + 4) * MB_STR + cn];
#pragma unroll
                for (int i = 0; i < 2; i++) {
                    mma_16n8k8(c[i][j], ah[i], bh);
                    mma_16n8k8(c[i][j], al[i], bh);
                    mma_16n8k8(c[i][j], ah[i], bl);
                }
            }
        }
    }

    // epilogue
#pragma unroll
    for (int i = 0; i < 2; i++) {
        int rowA = r0 + mrow + i * 16 + g;
        int rowB = rowA + 8;
        int gA = 0, gB = 0;
        if (ADD_GATHER) {
            if (rowA < n) gA = gidx[rowA];
            if (rowB < n) gB = gidx[rowB];
        }
#pragma unroll
        for (int j = 0; j < 8; j++) {
            int cn = ncol + j * 8 + 2 * t;
            if (rowA < n) {
                float2 o = make_float2(c[i][j][0], c[i][j][1]);
                if (ADD_GATHER) {
                    o.x += addsrc[(size_t)gA * 128 + cn];
                    o.y += addsrc[(size_t)gA * 128 + cn + 1];
                }
                *(float2*)&Cm[(size_t)rowA * 128 + cn] = o;
            }
            if (rowB < n) {
                float2 o = make_float2(c[i][j][2], c[i][j][3]);
                if (ADD_GATHER) {
                    o.x += addsrc[(size_t)gB * 128 + cn];
                    o.y += addsrc[(size_t)gB * 128 + cn + 1];
                }
                *(float2*)&Cm[(size_t)rowB * 128 + cn] = o;
            }
        }
    }
}

// ---------------- cluster max-pool ----------------
__global__ void k_poolmax(const float4* __restrict__ h, int* __restrict__ outb,
                          const int* __restrict__ clusters, int n) {
    int idx = blockIdx.x * blockDim.x + threadIdx.x;
    int node = idx >> 5, lane = idx & 31;
    if (node >= n) return;
    int c = clusters[node];
    float4 v = h[node * 32 + lane];
    int base = c * 128 + lane * 4;
    atomicMax(&outb[base + 0], __float_as_int(v.x));
    atomicMax(&outb[base + 1], __float_as_int(v.y));
    atomicMax(&outb[base + 2], __float_as_int(v.z));
    atomicMax(&outb[base + 3], __float_as_int(v.w));
}

// ---------------- output head ----------------
__global__ void k_head(const float4* __restrict__ h, const float* __restrict__ w,
                       const float* __restrict__ b, float* __restrict__ out, int n) {
    int idx = blockIdx.x * blockDim.x + threadIdx.x;
    int node = idx >> 5, lane = idx & 31;
    if (node >= n) return;
    float4 v = h[node * 32 + lane];
    int cb = lane * 4;
    float s = v.x * w[cb] + v.y * w[cb + 1] + v.z * w[cb + 2] + v.w * w[cb + 3];
#pragma unroll
    for (int off = 16; off > 0; off >>= 1) s += __shfl_down_sync(0xFFFFFFFFu, s, off);
    if (lane == 0) out[node] = s + b[0];
}

// ---------------- host ----------------
static inline void* symaddr(const void* sym) {
    void* p = nullptr;
    cudaGetSymbolAddress(&p, sym);
    return p;
}

extern "C" void kernel_launch(void* const* d_in, const int* in_sizes, int n_in,
                              void* d_out, int out_size) {
    const float* x     = (const float*)d_in[0];
    const int*   ei0   = (const int*)d_in[1];
    const int*   ei1   = (const int*)d_in[2];
    const int*   ei2   = (const int*)d_in[3];
    const int*   cl0   = (const int*)d_in[4];
    const int*   cl1   = (const int*)d_in[5];
    const float* w_e0a = (const float*)d_in[6];  const float* b_e0a = (const float*)d_in[7];
    const float* w_e0b = (const float*)d_in[8];  const float* b_e0b = (const float*)d_in[9];
    const float* w_e1a = (const float*)d_in[10]; const float* b_e1a = (const float*)d_in[11];
    const float* w_e1b = (const float*)d_in[12]; const float* b_e1b = (const float*)d_in[13];
    const float* w_ba  = (const float*)d_in[14]; const float* b_ba  = (const float*)d_in[15];
    const float* w_bb  = (const float*)d_in[16]; const float* b_bb  = (const float*)d_in[17];
    const float* w_d1a = (const float*)d_in[18]; const float* b_d1a = (const float*)d_in[19];
    const float* w_d1b = (const float*)d_in[20]; const float* b_d1b = (const float*)d_in[21];
    const float* w_d0a = (const float*)d_in[22]; const float* b_d0a = (const float*)d_in[23];
    const float* w_d0b = (const float*)d_in[24]; const float* b_d0b = (const float*)d_in[25];
    const float* w_out = (const float*)d_in[26]; const float* b_out = (const float*)d_in[27];
    float* out = (float*)d_out;

    float* A0 = (float*)symaddr(g_A0); float* B0 = (float*)symaddr(g_B0);
    float* E0f = (float*)symaddr(g_E0); float* T0 = (float*)symaddr(g_T0);
    float* X1 = (float*)symaddr(g_X1); float* A1 = (float*)symaddr(g_A1);
    float* B1 = (float*)symaddr(g_B1); float* E1f = (float*)symaddr(g_E1);
    float* X2 = (float*)symaddr(g_X2); float* A2 = (float*)symaddr(g_A2);
    float* BT = (float*)symaddr(g_BT);

    int* deg0 = (int*)symaddr(g_deg0); int* rp0 = (int*)symaddr(g_rp0); int* cur0 = (int*)symaddr(g_cur0);
    int* col0 = (int*)symaddr(g_col0); float* ws0 = (float*)symaddr(g_ws0); float* inv0 = (float*)symaddr(g_inv0);
    int* deg1 = (int*)symaddr(g_deg1); int* rp1 = (int*)symaddr(g_rp1); int* cur1 = (int*)symaddr(g_cur1);
    int* col1 = (int*)symaddr(g_col1); float* ws1 = (float*)symaddr(g_ws1); float* inv1 = (float*)symaddr(g_inv1);
    int* deg2 = (int*)symaddr(g_deg2); int* rp2 = (int*)symaddr(g_rp2); int* cur2 = (int*)symaddr(g_cur2);
    int* col2 = (int*)symaddr(g_col2); float* ws2 = (float*)symaddr(g_ws2); float* inv2 = (float*)symaddr(g_inv2);
    int* bs0 = (int*)symaddr(g_bsum0); int* bs1 = (int*)symaddr(g_bsum1); int* bs2 = (int*)symaddr(g_bsum2);

    cudaFuncSetAttribute(k_gemm_mma<false>, cudaFuncAttributeMaxDynamicSharedMemorySize, SM_TOT);
    cudaFuncSetAttribute(k_gemm_mma<true>,  cudaFuncAttributeMaxDynamicSharedMemorySize, SM_TOT);

    const int T = 256;
    dim3 aggB(32, 8);
    const int NB0 = (CN0 + SCAN_CHUNK - 1) / SCAN_CHUNK;
    const int NB1 = (CN1 + SCAN_CHUNK - 1) / SCAN_CHUNK;
    const int NB2 = (CN2 + SCAN_CHUNK - 1) / SCAN_CHUNK;
    const int GB0 = (CN0 + 127) / 128, GB1 = (CN1 + 127) / 128, GB2 = (CN2 + 127) / 128;

    // ---- CSR build ----
    cudaMemsetAsync(deg0, 0, CN0 * sizeof(int));
    cudaMemsetAsync(deg1, 0, CN1 * sizeof(int));
    cudaMemsetAsync(deg2, 0, CN2 * sizeof(int));
    k_deg<<<(CE0 + T - 1) / T, T>>>(ei0 + CE0, deg0, CE0);
    k_deg<<<(CE1 + T - 1) / T, T>>>(ei1 + CE1, deg1, CE1);
    k_deg<<<(CE2 + T - 1) / T, T>>>(ei2 + CE2, deg2, CE2);
    k_scan_part<<<NB0, 1024>>>(deg0, bs0, CN0);
    k_scan_part<<<NB1, 1024>>>(deg1, bs1, CN1);
    k_scan_part<<<NB2, 1024>>>(deg2, bs2, CN2);
    k_scan_top<<<1, 64>>>(bs0, NB0, rp0, CN0);
    k_scan_top<<<1, 64>>>(bs1, NB1, rp1, CN1);
    k_scan_top<<<1, 64>>>(bs2, NB2, rp2, CN2);
    k_scan_down<<<NB0, 1024>>>(deg0, bs0, rp0, cur0, inv0, CN0);
    k_scan_down<<<NB1, 1024>>>(deg1, bs1, rp1, cur1, inv1, CN1);
    k_scan_down<<<NB2, 1024>>>(deg2, bs2, rp2, cur2, inv2, CN2);
    k_fill<<<(CE0 + T - 1) / T, T>>>(ei0, ei0 + CE0, cur0, col0, ws0, inv0, CE0);
    k_fill<<<(CE1 + T - 1) / T, T>>>(ei1, ei1 + CE1, cur1, col1, ws1, inv1, CE1);
    k_fill<<<(CE2 + T - 1) / T, T>>>(ei2, ei2 + CE2, cur2, col2, ws2, inv2, CE2);

    // ---- encoder level 0 ----
    k_agg4<<<(CN0 + T - 1) / T, T>>>((const float4*)x, (float4*)T0, rp0, col0, ws0, inv0, CN0);
    k_gemm4<<<(CN0 * 32 + T - 1) / T, T>>>((const float4*)T0, w_e0a, b_e0a, (float4*)B0, CN0);
    k_gemm_mma<false><<<GB0, 256, SM_TOT>>>(B0, w_e0b, A0, CN0, nullptr, nullptr);
    k_agg128<<<(CN0 + 7) / 8, aggB>>>((const float4*)A0, (float4*)E0f, rp0, col0, ws0, inv0, b_e0b, CN0);

    // ---- pool 0 -> 1 ----
    cudaMemsetAsync(X1, 0, (size_t)CN1 * 128 * sizeof(float));
    k_poolmax<<<(CN0 * 32 + T - 1) / T, T>>>((const float4*)E0f, (int*)X1, cl0, CN0);

    // ---- encoder level 1 ----
    k_gemm_mma<false><<<GB1, 256, SM_TOT>>>(X1, w_e1a, A1, CN1, nullptr, nullptr);
    k_agg128<<<(CN1 + 7) / 8, aggB>>>((const float4*)A1, (float4*)B1, rp1, col1, ws1, inv1, b_e1a, CN1);
    k_gemm_mma<false><<<GB1, 256, SM_TOT>>>(B1, w_e1b, A1, CN1, nullptr, nullptr);
    k_agg128<<<(CN1 + 7) / 8, aggB>>>((const float4*)A1, (float4*)E1f, rp1, col1, ws1, inv1, b_e1b, CN1);

    // ---- pool 1 -> 2 ----
    cudaMemsetAsync(X2, 0, (size_t)CN2 * 128 * sizeof(float));
    k_poolmax<<<(CN1 * 32 + T - 1) / T, T>>>((const float4*)E1f, (int*)X2, cl1, CN1);

    // ---- bottom level 2 ----
    k_gemm_mma<false><<<GB2, 256, SM_TOT>>>(X2, w_ba, A2, CN2, nullptr, nullptr);
    k_agg128<<<(CN2 + 7) / 8, aggB>>>((const float4*)A2, (float4*)BT, rp2, col2, ws2, inv2, b_ba, CN2);
    k_gemm_mma<false><<<GB2, 256, SM_TOT>>>(BT, w_bb, A2, CN2, nullptr, nullptr);
    k_agg128<<<(CN2 + 7) / 8, aggB>>>((const float4*)A2, (float4*)BT, rp2, col2, ws2, inv2, b_bb, CN2);

    // ---- decoder level 1 ----
    k_gemm_mma<false><<<GB2, 256, SM_TOT>>>(BT, w_d1a, A2, CN2, nullptr, nullptr);              // y_top2
    k_gemm_mma<true><<<GB1, 256, SM_TOT>>>(E1f, w_d1a + 128 * 128, A1, CN1, A2, cl1);
    k_agg128<<<(CN1 + 7) / 8, aggB>>>((const float4*)A1, (float4*)B1, rp1, col1, ws1, inv1, b_d1a, CN1);
    k_gemm_mma<false><<<GB1, 256, SM_TOT>>>(B1, w_d1b, A1, CN1, nullptr, nullptr);
    k_agg128<<<(CN1 + 7) / 8, aggB>>>((const float4*)A1, (float4*)X1, rp1, col1, ws1, inv1, b_d1b, CN1);

    // ---- decoder level 0 ----
    k_gemm_mma<false><<<GB1, 256, SM_TOT>>>(X1, w_d0a, B1, CN1, nullptr, nullptr);              // y_top1
    k_gemm_mma<true><<<GB0, 256, SM_TOT>>>(E0f, w_d0a + 128 * 128, A0, CN0, B1, cl0);
    k_agg128<<<(CN0 + 7) / 8, aggB>>>((const float4*)A0, (float4*)B0, rp0, col0, ws0, inv0, b_d0a, CN0);
    k_gemm_mma<false><<<GB0, 256, SM_TOT>>>(B0, w_d0b, A0, CN0, nullptr, nullptr);
    k_agg128<<<(CN0 + 7) / 8, aggB>>>((const float4*)A0, (float4*)B0, rp0, col0, ws0, inv0, b_d0b, CN0);

    // ---- head ----
    k_head<<<(CN0 * 32 + T - 1) / T, T>>>((const float4*)B0, w_out, b_out, out, CN0);

    (void)in_sizes; (void)n_in; (void)out_size;
}

// round 5
// speedup vs baseline: 1.4800x; 1.4800x over previous
#include <cuda_runtime.h>
#include <cuda_bf16.h>
#include <cstdint>

#define CN0 200000
#define CN1 50000
#define CN2 12500
#define CE0 3200000
#define CE1 800000
#define CE2 200000

// ---------------- scratch (__device__ globals; no allocation allowed) ----------------
__device__ __align__(16) float g_A0[CN0 * 128];
__device__ __align__(16) float g_B0[CN0 * 128];
__device__ __align__(16) float g_E0[CN0 * 128];
__device__ __align__(16) float g_T0[CN0 * 4];
__device__ __align__(16) float g_X1[CN1 * 128];
__device__ __align__(16) float g_A1[CN1 * 128];
__device__ __align__(16) float g_B1[CN1 * 128];
__device__ __align__(16) float g_E1[CN1 * 128];
__device__ __align__(16) float g_X2[CN2 * 128];
__device__ __align__(16) float g_A2[CN2 * 128];
__device__ __align__(16) float g_BT[CN2 * 128];

__device__ int   g_deg0[CN0]; __device__ int g_rp0[CN0 + 1]; __device__ int g_cur0[CN0];
__device__ int   g_col0[CE0]; __device__ float g_ws0[CE0];   __device__ float g_inv0[CN0];
__device__ int   g_deg1[CN1]; __device__ int g_rp1[CN1 + 1]; __device__ int g_cur1[CN1];
__device__ int   g_col1[CE1]; __device__ float g_ws1[CE1];   __device__ float g_inv1[CN1];
__device__ int   g_deg2[CN2]; __device__ int g_rp2[CN2 + 1]; __device__ int g_cur2[CN2];
__device__ int   g_col2[CE2]; __device__ float g_ws2[CE2];   __device__ float g_inv2[CN2];

__device__ int g_bsum0[64];
__device__ int g_bsum1[16];
__device__ int g_bsum2[8];

#define SCAN_CHUNK 4096

// ---------------- CSR build ----------------
__global__ void k_deg(const int* __restrict__ dst, int* __restrict__ deg, int E) {
    int i = blockIdx.x * blockDim.x + threadIdx.x;
    if (i < E) atomicAdd(&deg[dst[i]], 1);
}

__global__ void k_scan_part(const int* __restrict__ deg, int* __restrict__ bsum, int n) {
    __shared__ int wsum[32];
    int base = blockIdx.x * SCAN_CHUNK + threadIdx.x * 4;
    int s = 0;
#pragma unroll
    for (int j = 0; j < 4; j++) if (base + j < n) s += deg[base + j];
    int lane = threadIdx.x & 31, wid = threadIdx.x >> 5;
#pragma unroll
    for (int off = 16; off > 0; off >>= 1) s += __shfl_down_sync(0xFFFFFFFFu, s, off);
    if (lane == 0) wsum[wid] = s;
    __syncthreads();
    if (threadIdx.x < 32) {
        int v = wsum[threadIdx.x];
#pragma unroll
        for (int off = 16; off > 0; off >>= 1) v += __shfl_down_sync(0xFFFFFFFFu, v, off);
        if (threadIdx.x == 0) bsum[blockIdx.x] = v;
    }
}

__global__ void k_scan_top(int* __restrict__ bsum, int nb, int* __restrict__ rp, int n) {
    int t = threadIdx.x;
    __shared__ int sh[64];
    sh[t] = (t < nb) ? bsum[t] : 0;
    __syncthreads();
    for (int off = 1; off < 64; off <<= 1) {
        int v = (t >= off) ? sh[t - off] : 0;
        __syncthreads();
        sh[t] += v;
        __syncthreads();
    }
    if (t < nb) bsum[t] = (t == 0) ? 0 : sh[t - 1];
    if (t == 63) rp[n] = sh[63];
}

__global__ void k_scan_down(const int* __restrict__ deg, const int* __restrict__ bsum,
                            int* __restrict__ rp, int* __restrict__ cur,
                            float* __restrict__ inv, int n) {
    __shared__ int wsum[32];
    int base = blockIdx.x * SCAN_CHUNK + threadIdx.x * 4;
    int d[4];
#pragma unroll
    for (int j = 0; j < 4; j++) d[j] = (base + j < n) ? deg[base + j] : 0;
    int tot = d[0] + d[1] + d[2] + d[3];
    int lane = threadIdx.x & 31, wid = threadIdx.x >> 5;
    int sc = tot;
#pragma unroll
    for (int off = 1; off < 32; off <<= 1) {
        int v = __shfl_up_sync(0xFFFFFFFFu, sc, off);
        if (lane >= off) sc += v;
    }
    if (lane == 31) wsum[wid] = sc;
    __syncthreads();
    if (threadIdx.x < 32) {
        int v = wsum[threadIdx.x];
#pragma unroll
        for (int off = 1; off < 32; off <<= 1) {
            int u = __shfl_up_sync(0xFFFFFFFFu, v, off);
            if (threadIdx.x >= off) v += u;
        }
        wsum[threadIdx.x] = v;
    }
    __syncthreads();
    int run = bsum[blockIdx.x] + (sc - tot) + (wid > 0 ? wsum[wid - 1] : 0);
#pragma unroll
    for (int j = 0; j < 4; j++) {
        if (base + j < n) {
            rp[base + j] = run;
            cur[base + j] = run;
            inv[base + j] = rsqrtf((float)(d[j] + 1));
            run += d[j];
        }
    }
}

__global__ void k_fill(const int* __restrict__ src, const int* __restrict__ dst,
                       int* __restrict__ cur, int* __restrict__ col,
                       float* __restrict__ ws, const float* __restrict__ inv, int E) {
    int i = blockIdx.x * blockDim.x + threadIdx.x;
    if (i >= E) return;
    int d = dst[i], s = src[i];
    int p = atomicAdd(&cur[d], 1);
    col[p] = s;
    ws[p] = inv[s];
}

// ---------------- aggregation over 4-wide features ----------------
__global__ void k_agg4(const float4* __restrict__ x, float4* __restrict__ out,
                       const int* __restrict__ rp, const int* __restrict__ col,
                       const float* __restrict__ ws, const float* __restrict__ inv, int n) {
    int r = blockIdx.x * blockDim.x + threadIdx.x;
    if (r >= n) return;
    float invd = inv[r];
    float4 xv = x[r];
    float c0 = invd * invd;
    float4 acc = make_float4(xv.x * c0, xv.y * c0, xv.z * c0, xv.w * c0);
    int e = rp[r], end = rp[r + 1];
    for (; e + 4 <= end; e += 4) {
        int s0 = col[e], s1 = col[e + 1], s2 = col[e + 2], s3 = col[e + 3];
        float w0 = ws[e] * invd, w1 = ws[e + 1] * invd, w2 = ws[e + 2] * invd, w3 = ws[e + 3] * invd;
        float4 v0 = x[s0], v1 = x[s1], v2 = x[s2], v3 = x[s3];
        acc.x += v0.x * w0 + v1.x * w1 + v2.x * w2 + v3.x * w3;
        acc.y += v0.y * w0 + v1.y * w1 + v2.y * w2 + v3.y * w3;
        acc.z += v0.z * w0 + v1.z * w1 + v2.z * w2 + v3.z * w3;
        acc.w += v0.w * w0 + v1.w * w1 + v2.w * w2 + v3.w * w3;
    }
    for (; e < end; e++) {
        int s0 = col[e]; float w0 = ws[e] * invd;
        float4 v0 = x[s0];
        acc.x += v0.x * w0; acc.y += v0.y * w0; acc.z += v0.z * w0; acc.w += v0.w * w0;
    }
    out[r] = acc;
}

// ---------------- aggregation over 128-wide features + bias + relu ----------------
__global__ void k_agg128(const float4* __restrict__ h, float4* __restrict__ out,
                         const int* __restrict__ rp, const int* __restrict__ col,
                         const float* __restrict__ ws, const float* __restrict__ inv,
                         const float* __restrict__ bias, int n) {
    int row = blockIdx.x * blockDim.y + threadIdx.y;
    if (row >= n) return;
    int lane = threadIdx.x;
    float invd = inv[row];
    float c0 = invd * invd;
    float4 hd = h[row * 32 + lane];
    float4 acc = make_float4(hd.x * c0, hd.y * c0, hd.z * c0, hd.w * c0);
    int e = rp[row], end = rp[row + 1];
    for (; e + 4 <= end; e += 4) {
        int s0 = col[e], s1 = col[e + 1], s2 = col[e + 2], s3 = col[e + 3];
        float w0 = ws[e] * invd, w1 = ws[e + 1] * invd, w2 = ws[e + 2] * invd, w3 = ws[e + 3] * invd;
        float4 v0 = h[s0 * 32 + lane];
        float4 v1 = h[s1 * 32 + lane];
        float4 v2 = h[s2 * 32 + lane];
        float4 v3 = h[s3 * 32 + lane];
        acc.x += v0.x * w0 + v1.x * w1 + v2.x * w2 + v3.x * w3;
        acc.y += v0.y * w0 + v1.y * w1 + v2.y * w2 + v3.y * w3;
        acc.z += v0.z * w0 + v1.z * w1 + v2.z * w2 + v3.z * w3;
        acc.w += v0.w * w0 + v1.w * w1 + v2.w * w2 + v3.w * w3;
    }
    for (; e < end; e++) {
        int s0 = col[e]; float w0 = ws[e] * invd;
        float4 v0 = h[s0 * 32 + lane];
        acc.x += v0.x * w0; acc.y += v0.y * w0; acc.z += v0.z * w0; acc.w += v0.w * w0;
    }
    int cb = lane * 4;
    acc.x = fmaxf(acc.x + bias[cb + 0], 0.f);
    acc.y = fmaxf(acc.y + bias[cb + 1], 0.f);
    acc.z = fmaxf(acc.z + bias[cb + 2], 0.f);
    acc.w = fmaxf(acc.w + bias[cb + 3], 0.f);
    out[row * 32 + lane] = acc;
}

// ---------------- K=4 GEMM with bias+relu ----------------
__global__ void k_gemm4(const float4* __restrict__ t, const float* __restrict__ W,
                        const float* __restrict__ bias, float4* __restrict__ out, int n) {
    __shared__ float Ws[4 * 128];
    __shared__ float Bs[128];
    int tid = threadIdx.x;
    for (int i = tid; i < 512; i += blockDim.x) Ws[i] = W[i];
    if (tid < 128) Bs[tid] = bias[tid];
    __syncthreads();
    int idx = blockIdx.x * blockDim.x + tid;
    int node = idx >> 5, lane = idx & 31;
    if (node >= n) return;
    float4 xv = t[node];
    int cb = lane * 4;
    float o[4];
#pragma unroll
    for (int j = 0; j < 4; j++) {
        o[j] = Bs[cb + j]
             + xv.x * Ws[0 * 128 + cb + j]
             + xv.y * Ws[1 * 128 + cb + j]
             + xv.z * Ws[2 * 128 + cb + j]
             + xv.w * Ws[3 * 128 + cb + j];
        o[j] = fmaxf(o[j], 0.f);
    }
    out[node * 32 + lane] = make_float4(o[0], o[1], o[2], o[3]);
}

// =====================================================================
//  bf16 mma.sync GEMM (m16n8k16, tensor pipe, 3xBF16 split):
//  C[n,128] = A[n,128] @ W[128,128] (+ gathered add).
//  Block: 256 thr / 8 warps, tile 128x128, warp tile 32x64.
//  Smem: bf16 pairs packed in u32, row stride 20 u32 (bank-conflict-free:
//  (20g+t) mod 32 all distinct for g<8,t<4). 40KB total -> 2 CTA/SM.
// =====================================================================
#define PS 20
#define SMB_AH 0
#define SMB_AL (128 * PS * 4)
#define SMB_BH (2 * 128 * PS * 4)
#define SMB_BL (3 * 128 * PS * 4)
#define SMB_TOT (4 * 128 * PS * 4)

__device__ __forceinline__ void bf16_split2(float a, float b, uint32_t& hi, uint32_t& lo) {
    // a = even-k element (low 16 bits), b = odd-k (high 16)
    __nv_bfloat16 ah = __float2bfloat16(a);
    __nv_bfloat16 bh = __float2bfloat16(b);
    __nv_bfloat16 al = __float2bfloat16(a - __bfloat162float(ah));
    __nv_bfloat16 bl = __float2bfloat16(b - __bfloat162float(bh));
    hi = ((uint32_t)__bfloat16_as_ushort(bh) << 16) | (uint32_t)__bfloat16_as_ushort(ah);
    lo = ((uint32_t)__bfloat16_as_ushort(bl) << 16) | (uint32_t)__bfloat16_as_ushort(al);
}

__device__ __forceinline__ void mma_bf16(float* c, const uint32_t* a, const uint32_t* b) {
    asm volatile(
        "mma.sync.aligned.m16n8k16.row.col.f32.bf16.bf16.f32 "
        "{%0,%1,%2,%3}, {%4,%5,%6,%7}, {%8,%9}, {%0,%1,%2,%3};"
        : "+f"(c[0]), "+f"(c[1]), "+f"(c[2]), "+f"(c[3])
        : "r"(a[0]), "r"(a[1]), "r"(a[2]), "r"(a[3]), "r"(b[0]), "r"(b[1]));
}

template <bool ADD_GATHER>
__global__ void __launch_bounds__(256, 2) k_gemm_mma(
    const float* __restrict__ A, const float* __restrict__ W,
    float* __restrict__ Cm, int n,
    const float* __restrict__ addsrc, const int* __restrict__ gidx) {
    extern __shared__ char smem[];
    uint32_t* AH = (uint32_t*)(smem + SMB_AH);
    uint32_t* AL = (uint32_t*)(smem + SMB_AL);
    uint32_t* BH = (uint32_t*)(smem + SMB_BH);
    uint32_t* BL = (uint32_t*)(smem + SMB_BL);

    int tid = threadIdx.x;
    int warp = tid >> 5, lane = tid & 31;
    int g = lane >> 2, t = lane & 3;
    int mrow = (warp & 3) * 32;
    int ncol = (warp >> 2) * 64;
    int r0 = blockIdx.x * 128;

    float c[2][8][4];
#pragma unroll
    for (int i = 0; i < 2; i++)
#pragma unroll
        for (int j = 0; j < 8; j++)
#pragma unroll
            for (int q = 0; q < 4; q++) c[i][j][q] = 0.f;

    for (int kc = 0; kc < 128; kc += 32) {
        __syncthreads();
        // A chunk [128 rows, 32 k] -> 2048 bf16-pairs, split hi/lo
#pragma unroll
        for (int it = 0; it < 8; it++) {
            int p = tid + it * 256;
            int row = p >> 4, kp = p & 15;
            float2 av = make_float2(0.f, 0.f);
            if (r0 + row < n) av = *(const float2*)&A[(size_t)(r0 + row) * 128 + kc + 2 * kp];
            uint32_t hi, lo;
            bf16_split2(av.x, av.y, hi, lo);
            AH[row * PS + kp] = hi;
            AL[row * PS + kp] = lo;
        }
        // W chunk [32 k, 128 n] -> stored k-pair-major per n: B[n][kp]
#pragma unroll
        for (int it = 0; it < 8; it++) {
            int p = tid + it * 256;
            int nn = p & 127, kp = p >> 7;
            float w0 = W[(size_t)(kc + 2 * kp) * 128 + nn];
            float w1 = W[(size_t)(kc + 2 * kp + 1) * 128 + nn];
            uint32_t hi, lo;
            bf16_split2(w0, w1, hi, lo);
            BH[nn * PS + kp] = hi;
            BL[nn * PS + kp] = lo;
        }
        __syncthreads();

#pragma unroll
        for (int ks = 0; ks < 2; ks++) {
            int pb = ks * 8;
            uint32_t ah[2][4], al[2][4];
#pragma unroll
            for (int i = 0; i < 2; i++) {
                int ra = mrow + i * 16 + g;
                ah[i][0] = AH[ra * PS + pb + t];
                ah[i][1] = AH[(ra + 8) * PS + pb + t];
                ah[i][2] = AH[ra * PS + pb + 4 + t];
                ah[i][3] = AH[(ra + 8) * PS + pb + 4 + t];
                al[i][0] = AL[ra * PS + pb + t];
                al[i][1] = AL[(ra + 8) * PS + pb + t];
                al[i][2] = AL[ra * PS + pb + 4 + t];
                al[i][3] = AL[(ra + 8) * PS + pb + 4 + t];
            }
#pragma unroll
            for (int j = 0; j < 8; j++) {
                int cn = ncol + j * 8 + g;
                uint32_t bh[2], bl[2];
                bh[0] = BH[cn * PS + pb + t];
                bh[1] = BH[cn * PS + pb + 4 + t];
                bl[0] = BL[cn * PS + pb + t];
                bl[1] = BL[cn * PS + pb + 4 + t];
#pragma unroll
                for (int i = 0; i < 2; i++) {
                    mma_bf16(c[i][j], ah[i], bh);
                    mma_bf16(c[i][j], al[i], bh);
                    mma_bf16(c[i][j], ah[i], bl);
                }
            }
        }
    }

    // epilogue
#pragma unroll
    for (int i = 0; i < 2; i++) {
        int rowA = r0 + mrow + i * 16 + g;
        int rowB = rowA + 8;
        int gA = 0, gB = 0;
        if (ADD_GATHER) {
            if (rowA < n) gA = gidx[rowA];
            if (rowB < n) gB = gidx[rowB];
        }
#pragma unroll
        for (int j = 0; j < 8; j++) {
            int cn = ncol + j * 8 + 2 * t;
            if (rowA < n) {
                float2 o = make_float2(c[i][j][0], c[i][j][1]);
                if (ADD_GATHER) {
                    o.x += addsrc[(size_t)gA * 128 + cn];
                    o.y += addsrc[(size_t)gA * 128 + cn + 1];
                }
                *(float2*)&Cm[(size_t)rowA * 128 + cn] = o;
            }
            if (rowB < n) {
                float2 o = make_float2(c[i][j][2], c[i][j][3]);
                if (ADD_GATHER) {
                    o.x += addsrc[(size_t)gB * 128 + cn];
                    o.y += addsrc[(size_t)gB * 128 + cn + 1];
                }
                *(float2*)&Cm[(size_t)rowB * 128 + cn] = o;
            }
        }
    }
}

// ---------------- cluster max-pool ----------------
__global__ void k_poolmax(const float4* __restrict__ h, int* __restrict__ outb,
                          const int* __restrict__ clusters, int n) {
    int idx = blockIdx.x * blockDim.x + threadIdx.x;
    int node = idx >> 5, lane = idx & 31;
    if (node >= n) return;
    int c = clusters[node];
    float4 v = h[node * 32 + lane];
    int base = c * 128 + lane * 4;
    atomicMax(&outb[base + 0], __float_as_int(v.x));
    atomicMax(&outb[base + 1], __float_as_int(v.y));
    atomicMax(&outb[base + 2], __float_as_int(v.z));
    atomicMax(&outb[base + 3], __float_as_int(v.w));
}

// ---------------- output head ----------------
__global__ void k_head(const float4* __restrict__ h, const float* __restrict__ w,
                       const float* __restrict__ b, float* __restrict__ out, int n) {
    int idx = blockIdx.x * blockDim.x + threadIdx.x;
    int node = idx >> 5, lane = idx & 31;
    if (node >= n) return;
    float4 v = h[node * 32 + lane];
    int cb = lane * 4;
    float s = v.x * w[cb] + v.y * w[cb + 1] + v.z * w[cb + 2] + v.w * w[cb + 3];
#pragma unroll
    for (int off = 16; off > 0; off >>= 1) s += __shfl_down_sync(0xFFFFFFFFu, s, off);
    if (lane == 0) out[node] = s + b[0];
}

// ---------------- host ----------------
static inline void* symaddr(const void* sym) {
    void* p = nullptr;
    cudaGetSymbolAddress(&p, sym);
    return p;
}

extern "C" void kernel_launch(void* const* d_in, const int* in_sizes, int n_in,
                              void* d_out, int out_size) {
    const float* x     = (const float*)d_in[0];
    const int*   ei0   = (const int*)d_in[1];
    const int*   ei1   = (const int*)d_in[2];
    const int*   ei2   = (const int*)d_in[3];
    const int*   cl0   = (const int*)d_in[4];
    const int*   cl1   = (const int*)d_in[5];
    const float* w_e0a = (const float*)d_in[6];  const float* b_e0a = (const float*)d_in[7];
    const float* w_e0b = (const float*)d_in[8];  const float* b_e0b = (const float*)d_in[9];
    const float* w_e1a = (const float*)d_in[10]; const float* b_e1a = (const float*)d_in[11];
    const float* w_e1b = (const float*)d_in[12]; const float* b_e1b = (const float*)d_in[13];
    const float* w_ba  = (const float*)d_in[14]; const float* b_ba  = (const float*)d_in[15];
    const float* w_bb  = (const float*)d_in[16]; const float* b_bb  = (const float*)d_in[17];
    const float* w_d1a = (const float*)d_in[18]; const float* b_d1a = (const float*)d_in[19];
    const float* w_d1b = (const float*)d_in[20]; const float* b_d1b = (const float*)d_in[21];
    const float* w_d0a = (const float*)d_in[22]; const float* b_d0a = (const float*)d_in[23];
    const float* w_d0b = (const float*)d_in[24]; const float* b_d0b = (const float*)d_in[25];
    const float* w_out = (const float*)d_in[26]; const float* b_out = (const float*)d_in[27];
    float* out = (float*)d_out;

    float* A0 = (float*)symaddr(g_A0); float* B0 = (float*)symaddr(g_B0);
    float* E0f = (float*)symaddr(g_E0); float* T0 = (float*)symaddr(g_T0);
    float* X1 = (float*)symaddr(g_X1); float* A1 = (float*)symaddr(g_A1);
    float* B1 = (float*)symaddr(g_B1); float* E1f = (float*)symaddr(g_E1);
    float* X2 = (float*)symaddr(g_X2); float* A2 = (float*)symaddr(g_A2);
    float* BT = (float*)symaddr(g_BT);

    int* deg0 = (int*)symaddr(g_deg0); int* rp0 = (int*)symaddr(g_rp0); int* cur0 = (int*)symaddr(g_cur0);
    int* col0 = (int*)symaddr(g_col0); float* ws0 = (float*)symaddr(g_ws0); float* inv0 = (float*)symaddr(g_inv0);
    int* deg1 = (int*)symaddr(g_deg1); int* rp1 = (int*)symaddr(g_rp1); int* cur1 = (int*)symaddr(g_cur1);
    int* col1 = (int*)symaddr(g_col1); float* ws1 = (float*)symaddr(g_ws1); float* inv1 = (float*)symaddr(g_inv1);
    int* deg2 = (int*)symaddr(g_deg2); int* rp2 = (int*)symaddr(g_rp2); int* cur2 = (int*)symaddr(g_cur2);
    int* col2 = (int*)symaddr(g_col2); float* ws2 = (float*)symaddr(g_ws2); float* inv2 = (float*)symaddr(g_inv2);
    int* bs0 = (int*)symaddr(g_bsum0); int* bs1 = (int*)symaddr(g_bsum1); int* bs2 = (int*)symaddr(g_bsum2);

    cudaFuncSetAttribute(k_gemm_mma<false>, cudaFuncAttributeMaxDynamicSharedMemorySize, SMB_TOT);
    cudaFuncSetAttribute(k_gemm_mma<true>,  cudaFuncAttributeMaxDynamicSharedMemorySize, SMB_TOT);

    const int T = 256;
    dim3 aggB(32, 8);
    const int NB0 = (CN0 + SCAN_CHUNK - 1) / SCAN_CHUNK;
    const int NB1 = (CN1 + SCAN_CHUNK - 1) / SCAN_CHUNK;
    const int NB2 = (CN2 + SCAN_CHUNK - 1) / SCAN_CHUNK;
    const int GB0 = (CN0 + 127) / 128, GB1 = (CN1 + 127) / 128, GB2 = (CN2 + 127) / 128;

    // ---- CSR build ----
    cudaMemsetAsync(deg0, 0, CN0 * sizeof(int));
    cudaMemsetAsync(deg1, 0, CN1 * sizeof(int));
    cudaMemsetAsync(deg2, 0, CN2 * sizeof(int));
    k_deg<<<(CE0 + T - 1) / T, T>>>(ei0 + CE0, deg0, CE0);
    k_deg<<<(CE1 + T - 1) / T, T>>>(ei1 + CE1, deg1, CE1);
    k_deg<<<(CE2 + T - 1) / T, T>>>(ei2 + CE2, deg2, CE2);
    k_scan_part<<<NB0, 1024>>>(deg0, bs0, CN0);
    k_scan_part<<<NB1, 1024>>>(deg1, bs1, CN1);
    k_scan_part<<<NB2, 1024>>>(deg2, bs2, CN2);
    k_scan_top<<<1, 64>>>(bs0, NB0, rp0, CN0);
    k_scan_top<<<1, 64>>>(bs1, NB1, rp1, CN1);
    k_scan_top<<<1, 64>>>(bs2, NB2, rp2, CN2);
    k_scan_down<<<NB0, 1024>>>(deg0, bs0, rp0, cur0, inv0, CN0);
    k_scan_down<<<NB1, 1024>>>(deg1, bs1, rp1, cur1, inv1, CN1);
    k_scan_down<<<NB2, 1024>>>(deg2, bs2, rp2, cur2, inv2, CN2);
    k_fill<<<(CE0 + T - 1) / T, T>>>(ei0, ei0 + CE0, cur0, col0, ws0, inv0, CE0);
    k_fill<<<(CE1 + T - 1) / T, T>>>(ei1, ei1 + CE1, cur1, col1, ws1, inv1, CE1);
    k_fill<<<(CE2 + T - 1) / T, T>>>(ei2, ei2 + CE2, cur2, col2, ws2, inv2, CE2);

    // ---- encoder level 0 ----
    k_agg4<<<(CN0 + T - 1) / T, T>>>((const float4*)x, (float4*)T0, rp0, col0, ws0, inv0, CN0);
    k_gemm4<<<(CN0 * 32 + T - 1) / T, T>>>((const float4*)T0, w_e0a, b_e0a, (float4*)B0, CN0);
    k_gemm_mma<false><<<GB0, 256, SMB_TOT>>>(B0, w_e0b, A0, CN0, nullptr, nullptr);
    k_agg128<<<(CN0 + 7) / 8, aggB>>>((const float4*)A0, (float4*)E0f, rp0, col0, ws0, inv0, b_e0b, CN0);

    // ---- pool 0 -> 1 ----
    cudaMemsetAsync(X1, 0, (size_t)CN1 * 128 * sizeof(float));
    k_poolmax<<<(CN0 * 32 + T - 1) / T, T>>>((const float4*)E0f, (int*)X1, cl0, CN0);

    // ---- encoder level 1 ----
    k_gemm_mma<false><<<GB1, 256, SMB_TOT>>>(X1, w_e1a, A1, CN1, nullptr, nullptr);
    k_agg128<<<(CN1 + 7) / 8, aggB>>>((const float4*)A1, (float4*)B1, rp1, col1, ws1, inv1, b_e1a, CN1);
    k_gemm_mma<false><<<GB1, 256, SMB_TOT>>>(B1, w_e1b, A1, CN1, nullptr, nullptr);
    k_agg128<<<(CN1 + 7) / 8, aggB>>>((const float4*)A1, (float4*)E1f, rp1, col1, ws1, inv1, b_e1b, CN1);

    // ---- pool 1 -> 2 ----
    cudaMemsetAsync(X2, 0, (size_t)CN2 * 128 * sizeof(float));
    k_poolmax<<<(CN1 * 32 + T - 1) / T, T>>>((const float4*)E1f, (int*)X2, cl1, CN1);

    // ---- bottom level 2 ----
    k_gemm_mma<false><<<GB2, 256, SMB_TOT>>>(X2, w_ba, A2, CN2, nullptr, nullptr);
    k_agg128<<<(CN2 + 7) / 8, aggB>>>((const float4*)A2, (float4*)BT, rp2, col2, ws2, inv2, b_ba, CN2);
    k_gemm_mma<false><<<GB2, 256, SMB_TOT>>>(BT, w_bb, A2, CN2, nullptr, nullptr);
    k_agg128<<<(CN2 + 7) / 8, aggB>>>((const float4*)A2, (float4*)BT, rp2, col2, ws2, inv2, b_bb, CN2);

    // ---- decoder level 1 ----
    k_gemm_mma<false><<<GB2, 256, SMB_TOT>>>(BT, w_d1a, A2, CN2, nullptr, nullptr);              // y_top2
    k_gemm_mma<true><<<GB1, 256, SMB_TOT>>>(E1f, w_d1a + 128 * 128, A1, CN1, A2, cl1);
    k_agg128<<<(CN1 + 7) / 8, aggB>>>((const float4*)A1, (float4*)B1, rp1, col1, ws1, inv1, b_d1a, CN1);
    k_gemm_mma<false><<<GB1, 256, SMB_TOT>>>(B1, w_d1b, A1, CN1, nullptr, nullptr);
    k_agg128<<<(CN1 + 7) / 8, aggB>>>((const float4*)A1, (float4*)X1, rp1, col1, ws1, inv1, b_d1b, CN1);

    // ---- decoder level 0 ----
    k_gemm_mma<false><<<GB1, 256, SMB_TOT>>>(X1, w_d0a, B1, CN1, nullptr, nullptr);              // y_top1
    k_gemm_mma<true><<<GB0, 256, SMB_TOT>>>(E0f, w_d0a + 128 * 128, A0, CN0, B1, cl0);
    k_agg128<<<(CN0 + 7) / 8, aggB>>>((const float4*)A0, (float4*)B0, rp0, col0, ws0, inv0, b_d0a, CN0);
    k_gemm_mma<false><<<GB0, 256, SMB_TOT>>>(B0, w_d0b, A0, CN0, nullptr, nullptr);
    k_agg128<<<(CN0 + 7) / 8, aggB>>>((const float4*)A0, (float4*)B0, rp0, col0, ws0, inv0, b_d0b, CN0);

    // ---- head ----
    k_head<<<(CN0 * 32 + T - 1) / T, T>>>((const float4*)B0, w_out, b_out, out, CN0);

    (void)in_sizes; (void)n_in; (void)out_size;
}